// round 1
// baseline (speedup 1.0000x reference)
#include <cuda_runtime.h>

#define N_C 16384
#define N_S 16384
#define D   2688
#define BK  16
#define KT  (D / BK)   // 168

// Scratch (no cudaMalloc allowed): style inverse norms + packed (val,idx) argmax.
__device__ float g_inv_s[N_S];
__device__ unsigned long long g_best[N_C];

// ---------------------------------------------------------------------------
// Reset per-row best keys (d_out is poisoned each run; g_best must be too).
// ---------------------------------------------------------------------------
__global__ void init_best_kernel() {
    int i = blockIdx.x * blockDim.x + threadIdx.x;
    if (i < N_C) g_best[i] = 0ULL;
}

// ---------------------------------------------------------------------------
// Style row inverse norms: one warp per row, float4 loads.
// ---------------------------------------------------------------------------
__global__ void style_norms_kernel(const float* __restrict__ S) {
    int row  = blockIdx.x * 8 + (threadIdx.x >> 5);
    int lane = threadIdx.x & 31;
    const float4* p = (const float4*)(S + (size_t)row * D);
    float sum = 0.f;
    for (int i = lane; i < D / 4; i += 32) {
        float4 v = p[i];
        sum += v.x * v.x;
        sum += v.y * v.y;
        sum += v.z * v.z;
        sum += v.w * v.w;
    }
#pragma unroll
    for (int o = 16; o; o >>= 1) sum += __shfl_xor_sync(0xffffffffu, sum, o);
    if (lane == 0) g_inv_s[row] = (float)(1.0 / sqrt((double)sum + 1e-8));
}

// ---------------------------------------------------------------------------
// Fused sim-GEMM + running argmax.
// Block: 256 threads, BM=128 content rows x BN=128 style cols per tile,
// double-buffered smem, 8x8 register micro-tile per thread.
// grid = (2 style halves, 128 M tiles) = 256 blocks (one resident wave @ occ 2).
// ---------------------------------------------------------------------------
__global__ __launch_bounds__(256, 2)
void sim_argmax_kernel(const float* __restrict__ C, const float* __restrict__ S) {
    __shared__ __align__(16) float As[2][BK][128];
    __shared__ __align__(16) float Bs[2][BK][128];

    const int tid = threadIdx.x;
    const int tx  = tid & 15;     // column group (8 cols)
    const int ty  = tid >> 4;     // row group    (8 rows)
    const int m_base  = blockIdx.y * 128;
    const int s_base0 = blockIdx.x * (N_S / 2);

    // global->smem load mapping: 512 float4 per tile, 2 per thread
    const int lrow = tid >> 2;    // 0..63
    const int lkv  = tid & 3;     // which float4 within the 16-wide K slab

    const float* Arow0 = C + (size_t)(m_base + lrow)      * D + lkv * 4;
    const float* Arow1 = C + (size_t)(m_base + 64 + lrow) * D + lkv * 4;

    float bestVal[8];
    int   bestIdx[8];
#pragma unroll
    for (int r = 0; r < 8; r++) { bestVal[r] = -3.0e38f; bestIdx[r] = 0; }

    for (int nt = 0; nt < (N_S / 2) / 128; ++nt) {
        const int s_base = s_base0 + nt * 128;
        const float* Brow0 = S + (size_t)(s_base + lrow)      * D + lkv * 4;
        const float* Brow1 = S + (size_t)(s_base + 64 + lrow) * D + lkv * 4;

        float acc[8][8];
#pragma unroll
        for (int i = 0; i < 8; i++)
#pragma unroll
            for (int j = 0; j < 8; j++) acc[i][j] = 0.f;

        // preload kt = 0 into buffer 0
        {
            float4 a0 = *(const float4*)(Arow0);
            float4 a1 = *(const float4*)(Arow1);
            float4 b0 = *(const float4*)(Brow0);
            float4 b1 = *(const float4*)(Brow1);
            const int kk = lkv * 4;
            As[0][kk + 0][lrow] = a0.x; As[0][kk + 1][lrow] = a0.y;
            As[0][kk + 2][lrow] = a0.z; As[0][kk + 3][lrow] = a0.w;
            As[0][kk + 0][64 + lrow] = a1.x; As[0][kk + 1][64 + lrow] = a1.y;
            As[0][kk + 2][64 + lrow] = a1.z; As[0][kk + 3][64 + lrow] = a1.w;
            Bs[0][kk + 0][lrow] = b0.x; Bs[0][kk + 1][lrow] = b0.y;
            Bs[0][kk + 2][lrow] = b0.z; Bs[0][kk + 3][lrow] = b0.w;
            Bs[0][kk + 0][64 + lrow] = b1.x; Bs[0][kk + 1][64 + lrow] = b1.y;
            Bs[0][kk + 2][64 + lrow] = b1.z; Bs[0][kk + 3][64 + lrow] = b1.w;
        }
        __syncthreads();

        for (int kt = 0; kt < KT; ++kt) {
            const int cur = kt & 1;
            const int nxt = cur ^ 1;

            float4 a0, a1, b0, b1;
            const bool more = (kt + 1 < KT);
            if (more) {
                const int k0 = (kt + 1) * BK;
                a0 = *(const float4*)(Arow0 + k0);
                a1 = *(const float4*)(Arow1 + k0);
                b0 = *(const float4*)(Brow0 + k0);
                b1 = *(const float4*)(Brow1 + k0);
            }

#pragma unroll
            for (int k = 0; k < BK; k++) {
                float a[8], b[8];
                *(float4*)&a[0] = *(const float4*)&As[cur][k][ty * 8];
                *(float4*)&a[4] = *(const float4*)&As[cur][k][ty * 8 + 4];
                *(float4*)&b[0] = *(const float4*)&Bs[cur][k][tx * 8];
                *(float4*)&b[4] = *(const float4*)&Bs[cur][k][tx * 8 + 4];
#pragma unroll
                for (int i = 0; i < 8; i++)
#pragma unroll
                    for (int j = 0; j < 8; j++)
                        acc[i][j] = fmaf(a[i], b[j], acc[i][j]);
            }

            if (more) {
                const int kk = lkv * 4;
                As[nxt][kk + 0][lrow] = a0.x; As[nxt][kk + 1][lrow] = a0.y;
                As[nxt][kk + 2][lrow] = a0.z; As[nxt][kk + 3][lrow] = a0.w;
                As[nxt][kk + 0][64 + lrow] = a1.x; As[nxt][kk + 1][64 + lrow] = a1.y;
                As[nxt][kk + 2][64 + lrow] = a1.z; As[nxt][kk + 3][64 + lrow] = a1.w;
                Bs[nxt][kk + 0][lrow] = b0.x; Bs[nxt][kk + 1][lrow] = b0.y;
                Bs[nxt][kk + 2][lrow] = b0.z; Bs[nxt][kk + 3][lrow] = b0.w;
                Bs[nxt][kk + 0][64 + lrow] = b1.x; Bs[nxt][kk + 1][64 + lrow] = b1.y;
                Bs[nxt][kk + 2][64 + lrow] = b1.z; Bs[nxt][kk + 3][64 + lrow] = b1.w;
            }
            __syncthreads();
        }

        // epilogue: scale by style inverse norm, update running argmax.
        // j ascending + strict '>' keeps the lowest index on ties (jnp.argmax).
#pragma unroll
        for (int j = 0; j < 8; j++) {
            const int n = s_base + tx * 8 + j;
            const float inv = g_inv_s[n];
#pragma unroll
            for (int i = 0; i < 8; i++) {
                float v = acc[i][j] * inv;
                if (v > bestVal[i]) { bestVal[i] = v; bestIdx[i] = n; }
            }
        }
    }

    // merge across threads/blocks: monotonic float encoding in high 32 bits,
    // (N_S-1-idx) in low 32 bits so equal values prefer the smaller index.
#pragma unroll
    for (int i = 0; i < 8; i++) {
        unsigned u = __float_as_uint(bestVal[i]);
        u = (u & 0x80000000u) ? ~u : (u | 0x80000000u);
        unsigned long long key =
            ((unsigned long long)u << 32) | (unsigned)(N_S - 1 - bestIdx[i]);
        atomicMax(&g_best[m_base + ty * 8 + i], key);
    }
}

// ---------------------------------------------------------------------------
// Gather un-normalized style rows into the output.
// ---------------------------------------------------------------------------
__global__ void gather_kernel(const float* __restrict__ S, float* __restrict__ out) {
    const int c = blockIdx.x;
    const unsigned long long key = g_best[c];
    const int idx = N_S - 1 - (int)(key & 0xffffffffu);
    const float4* src = (const float4*)(S + (size_t)idx * D);
    float4* dst = (float4*)(out + (size_t)c * D);
    for (int i = threadIdx.x; i < D / 4; i += blockDim.x) dst[i] = src[i];
}

extern "C" void kernel_launch(void* const* d_in, const int* in_sizes, int n_in,
                              void* d_out, int out_size) {
    const float* feats_c = (const float*)d_in[0];
    const float* feats_s = (const float*)d_in[1];
    float* out = (float*)d_out;

    init_best_kernel<<<N_C / 256, 256>>>();
    style_norms_kernel<<<N_S / 8, 256>>>(feats_s);
    dim3 grid(2, N_C / 128);
    sim_argmax_kernel<<<grid, 256>>>(feats_c, feats_s);
    gather_kernel<<<N_C, 256>>>(feats_s, out);
}

// round 6
// speedup vs baseline: 1.5046x; 1.5046x over previous
#include <cuda_runtime.h>
#include <cuda_fp16.h>
#include <cstdint>

#define N_C 16384
#define N_S 16384
#define DD  2688

#define BM 128
#define BN 128
#define BK 32                    // fp16 per K-chunk (64 B per row)
#define KCH (DD / BK)            // 84
#define NPASS 3                  // hi*hi, hi*lo, lo*hi
#define CPT (NPASS * KCH)        // 252 chunks per N-tile
#define NT (N_S / BN)            // 128 N-tiles (one CTA covers all)
#define GTOT (NT * CPT)          // 32256 chunks per CTA

#define STR 80                   // smem row stride: 64B data + 16B pad
#define ABYTES (128 * STR)       // 10240 per (A or B) tile

// ---------------- device scratch (symbols only touched in device code) ----------------
__device__ __half g_C_hi[(size_t)N_C * DD];
__device__ __half g_C_lo[(size_t)N_C * DD];
__device__ __half g_S_hi[(size_t)N_S * DD];
__device__ __half g_S_lo[(size_t)N_S * DD];
__device__ float g_inv_s[N_S];

// ---------------- helpers ----------------
__device__ __forceinline__ uint32_t smem_u32(const void* p) {
    uint32_t a;
    asm("{ .reg .u64 t; cvta.to.shared.u64 t, %1; cvt.u32.u64 %0, t; }" : "=r"(a) : "l"(p));
    return a;
}
__device__ __forceinline__ void ldsm_x4(uint32_t* r, uint32_t addr) {
    asm volatile("ldmatrix.sync.aligned.m8n8.x4.shared.b16 {%0,%1,%2,%3}, [%4];"
                 : "=r"(r[0]), "=r"(r[1]), "=r"(r[2]), "=r"(r[3]) : "r"(addr));
}
__device__ __forceinline__ void mma16816(float* c, const uint32_t* a,
                                         uint32_t b0, uint32_t b1) {
    asm volatile("mma.sync.aligned.m16n8k16.row.col.f32.f16.f16.f32 "
                 "{%0,%1,%2,%3}, {%4,%5,%6,%7}, {%8,%9}, {%0,%1,%2,%3};"
                 : "+f"(c[0]), "+f"(c[1]), "+f"(c[2]), "+f"(c[3])
                 : "r"(a[0]), "r"(a[1]), "r"(a[2]), "r"(a[3]), "r"(b0), "r"(b1));
}

// ---------------- small kernels ----------------
__global__ void style_norms_kernel(const float* __restrict__ S) {
    int row  = blockIdx.x * 8 + (threadIdx.x >> 5);
    int lane = threadIdx.x & 31;
    const float4* p = (const float4*)(S + (size_t)row * DD);
    float sum = 0.f;
    for (int i = lane; i < DD / 4; i += 32) {
        float4 v = p[i];
        sum += v.x * v.x + v.y * v.y + v.z * v.z + v.w * v.w;
    }
#pragma unroll
    for (int o = 16; o; o >>= 1) sum += __shfl_xor_sync(0xffffffffu, sum, o);
    if (lane == 0) g_inv_s[row] = (float)(1.0 / sqrt((double)sum + 1e-8));
}

// split fp32 -> (hi, lo) fp16 pairs; destination symbols resolved IN DEVICE CODE
// (passing __device__ arrays as kernel args from host was the R3-R5 bug).
__global__ void split_kernel(const float* __restrict__ X, int which, int n4) {
    int i = blockIdx.x * blockDim.x + threadIdx.x;
    if (i >= n4) return;
    __half* hi = which ? g_S_hi : g_C_hi;
    __half* lo = which ? g_S_lo : g_C_lo;
    float4 v = ((const float4*)X)[i];
    __half h0 = __float2half_rn(v.x);
    __half h1 = __float2half_rn(v.y);
    __half h2 = __float2half_rn(v.z);
    __half h3 = __float2half_rn(v.w);
    __half l0 = __float2half_rn(v.x - __half2float(h0));
    __half l1 = __float2half_rn(v.y - __half2float(h1));
    __half l2 = __float2half_rn(v.z - __half2float(h2));
    __half l3 = __float2half_rn(v.w - __half2float(h3));
    ushort4 hp, lp;
    hp.x = *(unsigned short*)&h0; hp.y = *(unsigned short*)&h1;
    hp.z = *(unsigned short*)&h2; hp.w = *(unsigned short*)&h3;
    lp.x = *(unsigned short*)&l0; lp.y = *(unsigned short*)&l1;
    lp.z = *(unsigned short*)&l2; lp.w = *(unsigned short*)&l3;
    ((ushort4*)hi)[i] = hp;
    ((ushort4*)lo)[i] = lp;
}

// ---------------- fully fused: GEMM + argmax + smem merge + gather ----------------
__global__ __launch_bounds__(256) void sim_mma_fused(const float* __restrict__ S,
                                                     float* __restrict__ out) {
    __shared__ __align__(16) char sbuf[4 * ABYTES];   // [A0|B0|A1|B1] = 40 KB

    const int tid = threadIdx.x;
    const int wid = tid >> 5;
    const int lid = tid & 31;
    const int wm  = wid >> 2;          // 0..1 : 64-row M half
    const int wn  = wid & 3;           // 0..3 : 32-col N quarter
    const int m_base = blockIdx.x * BM;

    const uint32_t sb = smem_u32(sbuf);

    // loader mapping: each thread stages 4 x 16B (A rows lrow,lrow+64; B same)
    const int lrow = tid >> 2;             // 0..63
    const int lseg = tid & 3;              // 16B segment within 64B row
    const uint32_t st_off = lrow * STR + lseg * 16;

    // ldmatrix per-lane components (byte offsets within a tile)
    const uint32_t a_lane = (uint32_t)(lid & 15) * STR + (uint32_t)(lid >> 4) * 16;
    const uint32_t b_lane = (uint32_t)(((lid >> 4) << 3) + (lid & 7)) * STR
                          + (uint32_t)((lid >> 3) & 1) * 16;

    float bestV[8];
    int   bestI[8];
#pragma unroll
    for (int i = 0; i < 8; i++) { bestV[i] = -3.0e38f; bestI[i] = 0; }

    // global load of chunk (p, kk, nt) into 4 regs
    uint4 r[4];
    auto gload = [&](int p, int kk, int t) {
        const __half* Asrc = (p < 2) ? g_C_hi : g_C_lo;
        const __half* Bsrc = (p == 1) ? g_S_lo : g_S_hi;
        const __half* Ab = Asrc + (size_t)(m_base + lrow) * DD + kk * BK + lseg * 8;
        const __half* Bb = Bsrc + (size_t)(t * BN + lrow) * DD + kk * BK + lseg * 8;
        r[0] = *(const uint4*)Ab;
        r[1] = *(const uint4*)(Ab + (size_t)64 * DD);
        r[2] = *(const uint4*)Bb;
        r[3] = *(const uint4*)(Bb + (size_t)64 * DD);
    };
    auto sstore = [&](int par) {
        char* base = sbuf + par * 2 * ABYTES;
        *(uint4*)(base + st_off)                    = r[0];
        *(uint4*)(base + st_off + 64 * STR)         = r[1];
        *(uint4*)(base + ABYTES + st_off)           = r[2];
        *(uint4*)(base + ABYTES + st_off + 64 * STR) = r[3];
    };

    float acc[4][4][4];
#pragma unroll
    for (int mf = 0; mf < 4; mf++)
#pragma unroll
        for (int nf = 0; nf < 4; nf++)
#pragma unroll
            for (int q = 0; q < 4; q++) acc[mf][nf][q] = 0.f;

    // stage chunk 0
    gload(0, 0, 0);
    sstore(0);
    __syncthreads();

    // incremental chunk indices: consumed (c, nt_c) / prefetched (p_f, kk_f, nt_f)
    int c = 0, nt_c = 0;
    int p_f = 0, kk_f = 1, nt_f = 0;   // chunk 1

#pragma unroll 1
    for (int g = 0; g < GTOT; ++g) {
        const int par = g & 1;
        const bool more = (g + 1 < GTOT);
        if (more) gload(p_f, kk_f, nt_f);

        // consume buffer `par`
        const uint32_t aS = sb + par * 2 * ABYTES;
        const uint32_t bS = aS + ABYTES;
#pragma unroll
        for (int ks = 0; ks < 2; ks++) {
            uint32_t a[4][4];
#pragma unroll
            for (int mf = 0; mf < 4; mf++)
                ldsm_x4(a[mf], aS + (wm * 64 + mf * 16) * STR + ks * 32 + a_lane);
            uint32_t b[2][4];
#pragma unroll
            for (int ng = 0; ng < 2; ng++)
                ldsm_x4(b[ng], bS + (wn * 32 + ng * 16) * STR + ks * 32 + b_lane);
#pragma unroll
            for (int mf = 0; mf < 4; mf++)
#pragma unroll
                for (int nf = 0; nf < 4; nf++)
                    mma16816(acc[mf][nf], a[mf],
                             b[nf >> 1][(nf & 1) * 2],
                             b[nf >> 1][(nf & 1) * 2 + 1]);
        }

        if (more) sstore(par ^ 1);
        __syncthreads();

        // end of an N-tile: fold scaled sims into running argmax, reset acc
        if (c == CPT - 1) {
#pragma unroll
            for (int nf = 0; nf < 4; nf++) {
                const int col0 = nt_c * BN + wn * 32 + nf * 8 + 2 * (lid & 3);
                const float inv0 = __ldg(&g_inv_s[col0]);
                const float inv1 = __ldg(&g_inv_s[col0 + 1]);
#pragma unroll
                for (int mf = 0; mf < 4; mf++) {
                    float v;
                    v = acc[mf][nf][0] * inv0;
                    if (v > bestV[2 * mf])     { bestV[2 * mf] = v;     bestI[2 * mf] = col0; }
                    v = acc[mf][nf][1] * inv1;
                    if (v > bestV[2 * mf])     { bestV[2 * mf] = v;     bestI[2 * mf] = col0 + 1; }
                    v = acc[mf][nf][2] * inv0;
                    if (v > bestV[2 * mf + 1]) { bestV[2 * mf + 1] = v; bestI[2 * mf + 1] = col0; }
                    v = acc[mf][nf][3] * inv1;
                    if (v > bestV[2 * mf + 1]) { bestV[2 * mf + 1] = v; bestI[2 * mf + 1] = col0 + 1; }
                }
            }
#pragma unroll
            for (int mf = 0; mf < 4; mf++)
#pragma unroll
                for (int nf = 0; nf < 4; nf++)
#pragma unroll
                    for (int q = 0; q < 4; q++) acc[mf][nf][q] = 0.f;
            c = 0; ++nt_c;
        } else {
            ++c;
        }

        if (more) {
            if (++kk_f == KCH) {
                kk_f = 0;
                if (++p_f == NPASS) { p_f = 0; ++nt_f; }
            }
        }
    }

    // ---- cross-warp merge through smem (reuse sbuf), then fused gather ----
    __syncthreads();
    unsigned long long* M = (unsigned long long*)sbuf;      // 128 rows x 16 slots
    int* sIdx = (int*)(sbuf + 16384);                       // 128 winners
    const int slot = wn * 4 + (lid & 3);
#pragma unroll
    for (int i = 0; i < 8; i++) {
        const int rl = wm * 64 + (i >> 1) * 16 + (lid >> 2) + (i & 1) * 8;
        unsigned u = __float_as_uint(bestV[i]);
        u = (u & 0x80000000u) ? ~u : (u | 0x80000000u);     // monotonic encoding
        M[rl * 16 + slot] = ((unsigned long long)u << 32)
                          | (unsigned)(N_S - 1 - bestI[i]); // ties -> min idx
    }
    __syncthreads();
    if (tid < 128) {
        unsigned long long best = M[tid * 16];
#pragma unroll
        for (int s = 1; s < 16; s++) {
            unsigned long long k = M[tid * 16 + s];
            if (k > best) best = k;
        }
        sIdx[tid] = N_S - 1 - (int)(best & 0xffffffffu);
    }
    __syncthreads();

    // gather: warp w copies rows w, w+8, ... (672 float4 per row)
    for (int rl = wid; rl < BM; rl += 8) {
        const int idx = sIdx[rl];
        const float4* src = (const float4*)(S + (size_t)idx * DD);
        float4* dst = (float4*)(out + (size_t)(m_base + rl) * DD);
        for (int i = lid; i < DD / 4; i += 32) dst[i] = src[i];
    }
}

extern "C" void kernel_launch(void* const* d_in, const int* in_sizes, int n_in,
                              void* d_out, int out_size) {
    const float* feats_c = (const float*)d_in[0];
    const float* feats_s = (const float*)d_in[1];
    float* out = (float*)d_out;

    style_norms_kernel<<<N_S / 8, 256>>>(feats_s);

    const int n4 = N_C * DD / 4;
    split_kernel<<<(n4 + 255) / 256, 256>>>(feats_c, 0, n4);
    split_kernel<<<(n4 + 255) / 256, 256>>>(feats_s, 1, n4);

    sim_mma_fused<<<N_C / BM, 256>>>(feats_s, out);
}

// round 7
// speedup vs baseline: 2.0979x; 1.3943x over previous
#include <cuda_runtime.h>
#include <cuda_fp16.h>
#include <cstdint>

#define N_C 16384
#define N_S 16384
#define DD  2688

#define BM 128
#define BN 128
#define BK 64                    // fp16 per K-chunk (128 B per row)
#define KCH (DD / BK)            // 42 chunks per N-tile (3 passes fused per chunk)
#define NT (N_S / BN)            // 128 N-tiles (one CTA covers all)
#define GTOT (NT * KCH)          // 5376 chunks per CTA

#define STR 144                  // smem row stride: 128B data + 16B pad
#define TILE_B (128 * STR)       // 18432 per tile
#define STAGE (4 * TILE_B)       // A_hi | A_lo | B_hi | B_lo = 73728
#define NSTAGE 3
#define SMEM_TOTAL (NSTAGE * STAGE)   // 221184

// ---------------- device scratch (symbols only touched in device code) ----------------
__device__ __half g_C_hi[(size_t)N_C * DD];
__device__ __half g_C_lo[(size_t)N_C * DD];
__device__ __half g_S_hi[(size_t)N_S * DD];
__device__ __half g_S_lo[(size_t)N_S * DD];
__device__ float g_inv_s[N_S];

// ---------------- helpers ----------------
__device__ __forceinline__ uint32_t smem_u32(const void* p) {
    uint32_t a;
    asm("{ .reg .u64 t; cvta.to.shared.u64 t, %1; cvt.u32.u64 %0, t; }" : "=r"(a) : "l"(p));
    return a;
}
__device__ __forceinline__ void cp16(uint32_t s, const void* g) {
    asm volatile("cp.async.cg.shared.global [%0], [%1], 16;" :: "r"(s), "l"(g));
}
#define CP_COMMIT() asm volatile("cp.async.commit_group;" ::: "memory")
#define CP_WAIT1()  asm volatile("cp.async.wait_group 1;" ::: "memory")

__device__ __forceinline__ void ldsm_x4(uint32_t* r, uint32_t addr) {
    asm volatile("ldmatrix.sync.aligned.m8n8.x4.shared.b16 {%0,%1,%2,%3}, [%4];"
                 : "=r"(r[0]), "=r"(r[1]), "=r"(r[2]), "=r"(r[3]) : "r"(addr));
}
__device__ __forceinline__ void mma16816(float* c, const uint32_t* a,
                                         uint32_t b0, uint32_t b1) {
    asm volatile("mma.sync.aligned.m16n8k16.row.col.f32.f16.f16.f32 "
                 "{%0,%1,%2,%3}, {%4,%5,%6,%7}, {%8,%9}, {%0,%1,%2,%3};"
                 : "+f"(c[0]), "+f"(c[1]), "+f"(c[2]), "+f"(c[3])
                 : "r"(a[0]), "r"(a[1]), "r"(a[2]), "r"(a[3]), "r"(b0), "r"(b1));
}

// ---------------- small kernels ----------------
__global__ void style_norms_kernel(const float* __restrict__ S) {
    int row  = blockIdx.x * 8 + (threadIdx.x >> 5);
    int lane = threadIdx.x & 31;
    const float4* p = (const float4*)(S + (size_t)row * DD);
    float sum = 0.f;
    for (int i = lane; i < DD / 4; i += 32) {
        float4 v = p[i];
        sum += v.x * v.x + v.y * v.y + v.z * v.z + v.w * v.w;
    }
#pragma unroll
    for (int o = 16; o; o >>= 1) sum += __shfl_xor_sync(0xffffffffu, sum, o);
    if (lane == 0) g_inv_s[row] = (float)(1.0 / sqrt((double)sum + 1e-8));
}

// split fp32 -> (hi, lo) fp16 pairs; destinations resolved IN DEVICE CODE.
__global__ void split_kernel(const float* __restrict__ X, int which, int n4) {
    int i = blockIdx.x * blockDim.x + threadIdx.x;
    if (i >= n4) return;
    __half* hi = which ? g_S_hi : g_C_hi;
    __half* lo = which ? g_S_lo : g_C_lo;
    float4 v = ((const float4*)X)[i];
    __half h0 = __float2half_rn(v.x);
    __half h1 = __float2half_rn(v.y);
    __half h2 = __float2half_rn(v.z);
    __half h3 = __float2half_rn(v.w);
    __half l0 = __float2half_rn(v.x - __half2float(h0));
    __half l1 = __float2half_rn(v.y - __half2float(h1));
    __half l2 = __float2half_rn(v.z - __half2float(h2));
    __half l3 = __float2half_rn(v.w - __half2float(h3));
    ushort4 hp, lp;
    hp.x = *(unsigned short*)&h0; hp.y = *(unsigned short*)&h1;
    hp.z = *(unsigned short*)&h2; hp.w = *(unsigned short*)&h3;
    lp.x = *(unsigned short*)&l0; lp.y = *(unsigned short*)&l1;
    lp.z = *(unsigned short*)&l2; lp.w = *(unsigned short*)&l3;
    ((ushort4*)hi)[i] = hp;
    ((ushort4*)lo)[i] = lp;
}

// ---------------- fused GEMM(3-term split) + argmax + merge + gather ----------------
__global__ __launch_bounds__(256, 1) void sim_mma_fused(const float* __restrict__ S,
                                                        float* __restrict__ out) {
    extern __shared__ __align__(16) char sbuf[];
    const uint32_t sb = smem_u32(sbuf);

    const int tid = threadIdx.x;
    const int wid = tid >> 5;
    const int lid = tid & 31;
    const int wm  = wid >> 2;          // 0..1 : 64-row M half
    const int wn  = wid & 3;           // 0..3 : 32-col N quarter
    const int m_base = blockIdx.x * BM;

    // loader mapping: per tile each thread stages 4 x 16B contiguous
    const int lrow = tid >> 1;             // 0..127
    const int lsg0 = (tid & 1) * 4;        // first 16B segment (of 8)
    const uint32_t st_off = lrow * STR + lsg0 * 16;

    // ldmatrix lane offsets (within-tile byte offsets)
    const uint32_t a_lane = (uint32_t)(lid & 15) * STR + (uint32_t)(lid >> 4) * 16;
    const uint32_t b_lane = (uint32_t)(((lid >> 4) << 3) + (lid & 7)) * STR
                          + (uint32_t)((lid >> 3) & 1) * 16;

    auto issue_loads = [&](int g) {
        const int kk = g % KCH;
        const int t  = g / KCH;
        const uint32_t st = sb + (g % NSTAGE) * STAGE;
        const __half* s0 = g_C_hi + (size_t)(m_base + lrow) * DD + kk * BK + lsg0 * 8;
        const __half* s1 = g_C_lo + (size_t)(m_base + lrow) * DD + kk * BK + lsg0 * 8;
        const __half* s2 = g_S_hi + (size_t)(t * BN + lrow) * DD + kk * BK + lsg0 * 8;
        const __half* s3 = g_S_lo + (size_t)(t * BN + lrow) * DD + kk * BK + lsg0 * 8;
#pragma unroll
        for (int j = 0; j < 4; j++) {
            cp16(st + 0 * TILE_B + st_off + j * 16, s0 + j * 8);
            cp16(st + 1 * TILE_B + st_off + j * 16, s1 + j * 8);
            cp16(st + 2 * TILE_B + st_off + j * 16, s2 + j * 8);
            cp16(st + 3 * TILE_B + st_off + j * 16, s3 + j * 8);
        }
        CP_COMMIT();
    };

    float bestV[8];
    int   bestI[8];
#pragma unroll
    for (int i = 0; i < 8; i++) { bestV[i] = -3.0e38f; bestI[i] = 0; }

    float acc[4][4][4];
#pragma unroll
    for (int mf = 0; mf < 4; mf++)
#pragma unroll
        for (int nf = 0; nf < 4; nf++)
#pragma unroll
            for (int q = 0; q < 4; q++) acc[mf][nf][q] = 0.f;

    issue_loads(0);
    issue_loads(1);

#pragma unroll 1
    for (int g = 0; g < GTOT; ++g) {
        CP_WAIT1();                    // stage g resident (<=1 group pending)
        __syncthreads();               // consumers of stage g-1 all done too
        if (g + 2 < GTOT) issue_loads(g + 2);
        else CP_COMMIT();              // empty group keeps accounting uniform

        const uint32_t st = sb + (g % NSTAGE) * STAGE;
        const uint32_t aHi = st;
        const uint32_t aLo = st + TILE_B;
        const uint32_t bHi = st + 2 * TILE_B;
        const uint32_t bLo = st + 3 * TILE_B;

#pragma unroll
        for (int ks = 0; ks < 4; ks++) {
            uint32_t bh[2][4], bl[2][4];
#pragma unroll
            for (int ng = 0; ng < 2; ng++) {
                ldsm_x4(bh[ng], bHi + (wn * 32 + ng * 16) * STR + ks * 32 + b_lane);
                ldsm_x4(bl[ng], bLo + (wn * 32 + ng * 16) * STR + ks * 32 + b_lane);
            }
            uint32_t a[4][4];
#pragma unroll
            for (int mf = 0; mf < 4; mf++)
                ldsm_x4(a[mf], aHi + (wm * 64 + mf * 16) * STR + ks * 32 + a_lane);
#pragma unroll
            for (int mf = 0; mf < 4; mf++)
#pragma unroll
                for (int nf = 0; nf < 4; nf++) {
                    mma16816(acc[mf][nf], a[mf],
                             bh[nf >> 1][(nf & 1) * 2], bh[nf >> 1][(nf & 1) * 2 + 1]);
                    mma16816(acc[mf][nf], a[mf],
                             bl[nf >> 1][(nf & 1) * 2], bl[nf >> 1][(nf & 1) * 2 + 1]);
                }
#pragma unroll
            for (int mf = 0; mf < 4; mf++)
                ldsm_x4(a[mf], aLo + (wm * 64 + mf * 16) * STR + ks * 32 + a_lane);
#pragma unroll
            for (int mf = 0; mf < 4; mf++)
#pragma unroll
                for (int nf = 0; nf < 4; nf++)
                    mma16816(acc[mf][nf], a[mf],
                             bh[nf >> 1][(nf & 1) * 2], bh[nf >> 1][(nf & 1) * 2 + 1]);
        }

        // end of an N-tile: fold scaled sims into running argmax, reset acc
        if (g % KCH == KCH - 1) {
            const int nt_c = g / KCH;
#pragma unroll
            for (int nf = 0; nf < 4; nf++) {
                const int col0 = nt_c * BN + wn * 32 + nf * 8 + 2 * (lid & 3);
                const float inv0 = __ldg(&g_inv_s[col0]);
                const float inv1 = __ldg(&g_inv_s[col0 + 1]);
#pragma unroll
                for (int mf = 0; mf < 4; mf++) {
                    float v;
                    v = acc[mf][nf][0] * inv0;
                    if (v > bestV[2 * mf])     { bestV[2 * mf] = v;     bestI[2 * mf] = col0; }
                    v = acc[mf][nf][1] * inv1;
                    if (v > bestV[2 * mf])     { bestV[2 * mf] = v;     bestI[2 * mf] = col0 + 1; }
                    v = acc[mf][nf][2] * inv0;
                    if (v > bestV[2 * mf + 1]) { bestV[2 * mf + 1] = v; bestI[2 * mf + 1] = col0; }
                    v = acc[mf][nf][3] * inv1;
                    if (v > bestV[2 * mf + 1]) { bestV[2 * mf + 1] = v; bestI[2 * mf + 1] = col0 + 1; }
                }
            }
#pragma unroll
            for (int mf = 0; mf < 4; mf++)
#pragma unroll
                for (int nf = 0; nf < 4; nf++)
#pragma unroll
                    for (int q = 0; q < 4; q++) acc[mf][nf][q] = 0.f;
        }
    }

    // ---- cross-warp merge through smem (reuse sbuf), then fused gather ----
    __syncthreads();
    unsigned long long* M = (unsigned long long*)sbuf;      // 128 rows x 16 slots
    int* sIdx = (int*)(sbuf + 16384);                       // 128 winners
    const int slot = wn * 4 + (lid & 3);
#pragma unroll
    for (int i = 0; i < 8; i++) {
        const int rl = wm * 64 + (i >> 1) * 16 + (lid >> 2) + (i & 1) * 8;
        unsigned u = __float_as_uint(bestV[i]);
        u = (u & 0x80000000u) ? ~u : (u | 0x80000000u);     // monotonic encoding
        M[rl * 16 + slot] = ((unsigned long long)u << 32)
                          | (unsigned)(N_S - 1 - bestI[i]); // ties -> min idx
    }
    __syncthreads();
    if (tid < 128) {
        unsigned long long best = M[tid * 16];
#pragma unroll
        for (int s = 1; s < 16; s++) {
            unsigned long long k = M[tid * 16 + s];
            if (k > best) best = k;
        }
        sIdx[tid] = N_S - 1 - (int)(best & 0xffffffffu);
    }
    __syncthreads();

    // gather: warp w copies rows w, w+8, ... (672 float4 per row)
    for (int rl = wid; rl < BM; rl += 8) {
        const int idx = sIdx[rl];
        const float4* src = (const float4*)(S + (size_t)idx * DD);
        float4* dst = (float4*)(out + (size_t)(m_base + rl) * DD);
        for (int i = lid; i < DD / 4; i += 32) dst[i] = src[i];
    }
}

extern "C" void kernel_launch(void* const* d_in, const int* in_sizes, int n_in,
                              void* d_out, int out_size) {
    const float* feats_c = (const float*)d_in[0];
    const float* feats_s = (const float*)d_in[1];
    float* out = (float*)d_out;

    cudaFuncSetAttribute(sim_mma_fused,
                         cudaFuncAttributeMaxDynamicSharedMemorySize, SMEM_TOTAL);

    style_norms_kernel<<<N_S / 8, 256>>>(feats_s);

    const int n4 = N_C * DD / 4;
    split_kernel<<<(n4 + 255) / 256, 256>>>(feats_c, 0, n4);
    split_kernel<<<(n4 + 255) / 256, 256>>>(feats_s, 1, n4);

    sim_mma_fused<<<N_C / BM, 256, SMEM_TOTAL>>>(feats_s, out);
}

// round 8
// speedup vs baseline: 2.4508x; 1.1682x over previous
#include <cuda_runtime.h>
#include <cuda_fp16.h>
#include <cstdint>

#define N_C 16384
#define N_S 16384
#define DD  2688

#define BM 128
#define BN 128
#define BK 64                    // fp16 per K-chunk (128 B per row)
#define KCH (DD / BK)            // 42 chunks per N-tile (3 split-terms fused per chunk)
#define NT (N_S / BN)            // 128 N-tiles (one CTA covers all)
#define GTOT (NT * KCH)          // 5376 chunks per CTA

#define STR 144                  // smem row stride: 128B data + 16B pad
#define TILE_B (128 * STR)       // 18432 per tile
#define STAGE (4 * TILE_B)       // A_hi | A_lo | B_hi | B_lo = 73728
#define NSTAGE 3
#define SMEM_TOTAL (NSTAGE * STAGE)   // 221184

#define NTHREADS 512

// ---------------- device scratch (symbols only touched in device code) ----------------
__device__ __half g_C_hi[(size_t)N_C * DD];
__device__ __half g_C_lo[(size_t)N_C * DD];
__device__ __half g_S_hi[(size_t)N_S * DD];
__device__ __half g_S_lo[(size_t)N_S * DD];
__device__ float g_inv_s[N_S];

// ---------------- helpers ----------------
__device__ __forceinline__ uint32_t smem_u32(const void* p) {
    uint32_t a;
    asm("{ .reg .u64 t; cvta.to.shared.u64 t, %1; cvt.u32.u64 %0, t; }" : "=r"(a) : "l"(p));
    return a;
}
__device__ __forceinline__ void cp16(uint32_t s, const void* g) {
    asm volatile("cp.async.cg.shared.global [%0], [%1], 16;" :: "r"(s), "l"(g));
}
#define CP_COMMIT() asm volatile("cp.async.commit_group;" ::: "memory")
#define CP_WAIT1()  asm volatile("cp.async.wait_group 1;" ::: "memory")

__device__ __forceinline__ void ldsm_x4(uint32_t* r, uint32_t addr) {
    asm volatile("ldmatrix.sync.aligned.m8n8.x4.shared.b16 {%0,%1,%2,%3}, [%4];"
                 : "=r"(r[0]), "=r"(r[1]), "=r"(r[2]), "=r"(r[3]) : "r"(addr));
}
__device__ __forceinline__ void mma16816(float* c, const uint32_t* a,
                                         uint32_t b0, uint32_t b1) {
    asm volatile("mma.sync.aligned.m16n8k16.row.col.f32.f16.f16.f32 "
                 "{%0,%1,%2,%3}, {%4,%5,%6,%7}, {%8,%9}, {%0,%1,%2,%3};"
                 : "+f"(c[0]), "+f"(c[1]), "+f"(c[2]), "+f"(c[3])
                 : "r"(a[0]), "r"(a[1]), "r"(a[2]), "r"(a[3]), "r"(b0), "r"(b1));
}

// ---------------- small kernels ----------------
__global__ void style_norms_kernel(const float* __restrict__ S) {
    int row  = blockIdx.x * 8 + (threadIdx.x >> 5);
    int lane = threadIdx.x & 31;
    const float4* p = (const float4*)(S + (size_t)row * DD);
    float sum = 0.f;
    for (int i = lane; i < DD / 4; i += 32) {
        float4 v = p[i];
        sum += v.x * v.x + v.y * v.y + v.z * v.z + v.w * v.w;
    }
#pragma unroll
    for (int o = 16; o; o >>= 1) sum += __shfl_xor_sync(0xffffffffu, sum, o);
    if (lane == 0) g_inv_s[row] = (float)(1.0 / sqrt((double)sum + 1e-8));
}

// split fp32 -> (hi, lo) fp16 pairs; destinations resolved IN DEVICE CODE.
__global__ void split_kernel(const float* __restrict__ X, int which, int n4) {
    int i = blockIdx.x * blockDim.x + threadIdx.x;
    if (i >= n4) return;
    __half* hi = which ? g_S_hi : g_C_hi;
    __half* lo = which ? g_S_lo : g_C_lo;
    float4 v = ((const float4*)X)[i];
    __half h0 = __float2half_rn(v.x);
    __half h1 = __float2half_rn(v.y);
    __half h2 = __float2half_rn(v.z);
    __half h3 = __float2half_rn(v.w);
    __half l0 = __float2half_rn(v.x - __half2float(h0));
    __half l1 = __float2half_rn(v.y - __half2float(h1));
    __half l2 = __float2half_rn(v.z - __half2float(h2));
    __half l3 = __float2half_rn(v.w - __half2float(h3));
    ushort4 hp, lp;
    hp.x = *(unsigned short*)&h0; hp.y = *(unsigned short*)&h1;
    hp.z = *(unsigned short*)&h2; hp.w = *(unsigned short*)&h3;
    lp.x = *(unsigned short*)&l0; lp.y = *(unsigned short*)&l1;
    lp.z = *(unsigned short*)&l2; lp.w = *(unsigned short*)&l3;
    ((ushort4*)hi)[i] = hp;
    ((ushort4*)lo)[i] = lp;
}

// ---------------- fused GEMM(3-term split) + argmax + merge + gather ----------------
// 512 threads: 16 warps in a 4(M) x 4(N) grid, 32x32 tile per warp.
__global__ __launch_bounds__(NTHREADS, 1) void sim_mma_fused(const float* __restrict__ S,
                                                             float* __restrict__ out) {
    extern __shared__ __align__(16) char sbuf[];
    const uint32_t sb = smem_u32(sbuf);

    const int tid = threadIdx.x;
    const int wid = tid >> 5;
    const int lid = tid & 31;
    const int wm  = wid >> 2;          // 0..3 : 32-row M quarter
    const int wn  = wid & 3;           // 0..3 : 32-col N quarter
    const int m_base = blockIdx.x * BM;

    // loader: per tile each thread stages 2 x 16B (row = tid>>2, segs s, s+4)
    const int lrow = tid >> 2;             // 0..127
    const int lsg  = tid & 3;              // segments lsg and lsg+4
    const uint32_t st_off = lrow * STR + lsg * 16;

    // ldmatrix lane offsets (within-tile byte offsets)
    const uint32_t a_lane = (uint32_t)(lid & 15) * STR + (uint32_t)(lid >> 4) * 16;
    const uint32_t b_lane = (uint32_t)(((lid >> 4) << 3) + (lid & 7)) * STR
                          + (uint32_t)((lid >> 3) & 1) * 16;

    auto issue_loads = [&](int g) {
        const int kk = g % KCH;
        const int t  = g / KCH;
        const uint32_t st = sb + (g % NSTAGE) * STAGE;
        const size_t aoff = (size_t)(m_base + lrow) * DD + kk * BK + lsg * 8;
        const size_t boff = (size_t)(t * BN + lrow) * DD + kk * BK + lsg * 8;
        cp16(st + 0 * TILE_B + st_off,      g_C_hi + aoff);
        cp16(st + 0 * TILE_B + st_off + 64, g_C_hi + aoff + 32);
        cp16(st + 1 * TILE_B + st_off,      g_C_lo + aoff);
        cp16(st + 1 * TILE_B + st_off + 64, g_C_lo + aoff + 32);
        cp16(st + 2 * TILE_B + st_off,      g_S_hi + boff);
        cp16(st + 2 * TILE_B + st_off + 64, g_S_hi + boff + 32);
        cp16(st + 3 * TILE_B + st_off,      g_S_lo + boff);
        cp16(st + 3 * TILE_B + st_off + 64, g_S_lo + boff + 32);
        CP_COMMIT();
    };

    float bestV[4];
    int   bestI[4];
#pragma unroll
    for (int i = 0; i < 4; i++) { bestV[i] = -3.0e38f; bestI[i] = 0; }

    float acc[2][4][4];
#pragma unroll
    for (int mf = 0; mf < 2; mf++)
#pragma unroll
        for (int nf = 0; nf < 4; nf++)
#pragma unroll
            for (int q = 0; q < 4; q++) acc[mf][nf][q] = 0.f;

    issue_loads(0);
    issue_loads(1);

#pragma unroll 1
    for (int g = 0; g < GTOT; ++g) {
        CP_WAIT1();                    // stage g resident (<=1 group pending)
        __syncthreads();               // consumers of stage g-1 all done too
        if (g + 2 < GTOT) issue_loads(g + 2);
        else CP_COMMIT();              // empty group keeps accounting uniform

        const uint32_t st = sb + (g % NSTAGE) * STAGE;
        const uint32_t aHi = st;
        const uint32_t aLo = st + TILE_B;
        const uint32_t bHi = st + 2 * TILE_B;
        const uint32_t bLo = st + 3 * TILE_B;

#pragma unroll
        for (int ks = 0; ks < 4; ks++) {
            uint32_t bh[2][4], bl[2][4];
#pragma unroll
            for (int ng = 0; ng < 2; ng++) {
                ldsm_x4(bh[ng], bHi + (wn * 32 + ng * 16) * STR + ks * 32 + b_lane);
                ldsm_x4(bl[ng], bLo + (wn * 32 + ng * 16) * STR + ks * 32 + b_lane);
            }
            uint32_t a[2][4];
#pragma unroll
            for (int mf = 0; mf < 2; mf++)
                ldsm_x4(a[mf], aHi + (wm * 32 + mf * 16) * STR + ks * 32 + a_lane);
#pragma unroll
            for (int mf = 0; mf < 2; mf++)
#pragma unroll
                for (int nf = 0; nf < 4; nf++) {
                    mma16816(acc[mf][nf], a[mf],
                             bh[nf >> 1][(nf & 1) * 2], bh[nf >> 1][(nf & 1) * 2 + 1]);
                    mma16816(acc[mf][nf], a[mf],
                             bl[nf >> 1][(nf & 1) * 2], bl[nf >> 1][(nf & 1) * 2 + 1]);
                }
            // overwrite a with the lo fragments (hi no longer needed this ks)
#pragma unroll
            for (int mf = 0; mf < 2; mf++)
                ldsm_x4(a[mf], aLo + (wm * 32 + mf * 16) * STR + ks * 32 + a_lane);
#pragma unroll
            for (int mf = 0; mf < 2; mf++)
#pragma unroll
                for (int nf = 0; nf < 4; nf++)
                    mma16816(acc[mf][nf], a[mf],
                             bh[nf >> 1][(nf & 1) * 2], bh[nf >> 1][(nf & 1) * 2 + 1]);
        }

        // end of an N-tile: fold scaled sims into running argmax, reset acc
        if (g % KCH == KCH - 1) {
            const int nt_c = g / KCH;
#pragma unroll
            for (int nf = 0; nf < 4; nf++) {
                const int col0 = nt_c * BN + wn * 32 + nf * 8 + 2 * (lid & 3);
                const float inv0 = __ldg(&g_inv_s[col0]);
                const float inv1 = __ldg(&g_inv_s[col0 + 1]);
#pragma unroll
                for (int mf = 0; mf < 2; mf++) {
                    float v;
                    v = acc[mf][nf][0] * inv0;
                    if (v > bestV[2 * mf])     { bestV[2 * mf] = v;     bestI[2 * mf] = col0; }
                    v = acc[mf][nf][1] * inv1;
                    if (v > bestV[2 * mf])     { bestV[2 * mf] = v;     bestI[2 * mf] = col0 + 1; }
                    v = acc[mf][nf][2] * inv0;
                    if (v > bestV[2 * mf + 1]) { bestV[2 * mf + 1] = v; bestI[2 * mf + 1] = col0; }
                    v = acc[mf][nf][3] * inv1;
                    if (v > bestV[2 * mf + 1]) { bestV[2 * mf + 1] = v; bestI[2 * mf + 1] = col0 + 1; }
                }
            }
#pragma unroll
            for (int mf = 0; mf < 2; mf++)
#pragma unroll
                for (int nf = 0; nf < 4; nf++)
#pragma unroll
                    for (int q = 0; q < 4; q++) acc[mf][nf][q] = 0.f;
        }
    }

    // ---- cross-warp merge through smem (reuse sbuf), then fused gather ----
    __syncthreads();
    unsigned long long* M = (unsigned long long*)sbuf;      // 128 rows x 16 slots
    int* sIdx = (int*)(sbuf + 16384);                       // 128 winners
    const int slot = wn * 4 + (lid & 3);
#pragma unroll
    for (int i = 0; i < 4; i++) {
        const int rl = wm * 32 + (i >> 1) * 16 + (lid >> 2) + (i & 1) * 8;
        unsigned u = __float_as_uint(bestV[i]);
        u = (u & 0x80000000u) ? ~u : (u | 0x80000000u);     // monotonic encoding
        M[rl * 16 + slot] = ((unsigned long long)u << 32)
                          | (unsigned)(N_S - 1 - bestI[i]); // ties -> min idx
    }
    __syncthreads();
    if (tid < 128) {
        unsigned long long best = M[tid * 16];
#pragma unroll
        for (int s = 1; s < 16; s++) {
            unsigned long long k = M[tid * 16 + s];
            if (k > best) best = k;
        }
        sIdx[tid] = N_S - 1 - (int)(best & 0xffffffffu);
    }
    __syncthreads();

    // gather: warp w copies rows w, w+16, ... (672 float4 per row)
    for (int rl = wid; rl < BM; rl += 16) {
        const int idx = sIdx[rl];
        const float4* src = (const float4*)(S + (size_t)idx * DD);
        float4* dst = (float4*)(out + (size_t)(m_base + rl) * DD);
        for (int i = lid; i < DD / 4; i += 32) dst[i] = src[i];
    }
}

extern "C" void kernel_launch(void* const* d_in, const int* in_sizes, int n_in,
                              void* d_out, int out_size) {
    const float* feats_c = (const float*)d_in[0];
    const float* feats_s = (const float*)d_in[1];
    float* out = (float*)d_out;

    cudaFuncSetAttribute(sim_mma_fused,
                         cudaFuncAttributeMaxDynamicSharedMemorySize, SMEM_TOTAL);

    style_norms_kernel<<<N_S / 8, 256>>>(feats_s);

    const int n4 = N_C * DD / 4;
    split_kernel<<<(n4 + 255) / 256, 256>>>(feats_c, 0, n4);
    split_kernel<<<(n4 + 255) / 256, 256>>>(feats_s, 1, n4);

    sim_mma_fused<<<N_C / BM, NTHREADS, SMEM_TOTAL>>>(feats_s, out);
}

// round 9
// speedup vs baseline: 6.6004x; 2.6931x over previous
#include <cuda_runtime.h>
#include <cuda_fp16.h>
#include <cstdint>

#define N_C 16384
#define N_S 16384
#define DD  2688

#define BM 128
#define BN 256
#define BK 64                     // fp16 per K-chunk (128 B rows)
#define KCH (DD / BK)             // 42
#define NT (N_S / BN)             // 64
#define GTOT (NT * KCH)           // 2688 chunks per CTA

#define STR 144                   // smem row stride: 128B data + 16B pad
#define A_TILE (128 * STR)        // 18432
#define B_TILE (256 * STR)        // 36864
#define STAGE (A_TILE + B_TILE)   // 55296
#define NSTAGE 3
#define SMEM_TOTAL (NSTAGE * STAGE)  // 165888

#define NTHREADS 512
#define CAP 384
#define TAU 0.008f

// ---------------- device scratch (symbols only touched in device code) ----------------
__device__ __half g_C_hi[(size_t)N_C * DD];
__device__ __half g_S_hi[(size_t)N_S * DD];
__device__ float g_inv_s[N_S];
__device__ float g_rowmax[N_C];
__device__ int   g_cnt[N_C];
__device__ unsigned long long g_cand[(size_t)N_C * CAP];

// ---------------- helpers ----------------
__device__ __forceinline__ uint32_t smem_u32(const void* p) {
    uint32_t a;
    asm("{ .reg .u64 t; cvta.to.shared.u64 t, %1; cvt.u32.u64 %0, t; }" : "=r"(a) : "l"(p));
    return a;
}
__device__ __forceinline__ void cp16(uint32_t s, const void* g) {
    asm volatile("cp.async.cg.shared.global [%0], [%1], 16;" :: "r"(s), "l"(g));
}
#define CP_COMMIT() asm volatile("cp.async.commit_group;" ::: "memory")
#define CP_WAIT1()  asm volatile("cp.async.wait_group 1;" ::: "memory")

__device__ __forceinline__ void ldsm_x4(uint32_t* r, uint32_t addr) {
    asm volatile("ldmatrix.sync.aligned.m8n8.x4.shared.b16 {%0,%1,%2,%3}, [%4];"
                 : "=r"(r[0]), "=r"(r[1]), "=r"(r[2]), "=r"(r[3]) : "r"(addr));
}
__device__ __forceinline__ void mma16816(float* c, const uint32_t* a,
                                         uint32_t b0, uint32_t b1) {
    asm volatile("mma.sync.aligned.m16n8k16.row.col.f32.f16.f16.f32 "
                 "{%0,%1,%2,%3}, {%4,%5,%6,%7}, {%8,%9}, {%0,%1,%2,%3};"
                 : "+f"(c[0]), "+f"(c[1]), "+f"(c[2]), "+f"(c[3])
                 : "r"(a[0]), "r"(a[1]), "r"(a[2]), "r"(a[3]), "r"(b0), "r"(b1));
}

// ---------------- small kernels ----------------
__global__ void init_cnt_kernel() {
    int i = blockIdx.x * blockDim.x + threadIdx.x;
    if (i < N_C) g_cnt[i] = 0;
}

__global__ void style_norms_kernel(const float* __restrict__ S) {
    int row  = blockIdx.x * 8 + (threadIdx.x >> 5);
    int lane = threadIdx.x & 31;
    const float4* p = (const float4*)(S + (size_t)row * DD);
    float sum = 0.f;
    for (int i = lane; i < DD / 4; i += 32) {
        float4 v = p[i];
        sum += v.x * v.x + v.y * v.y + v.z * v.z + v.w * v.w;
    }
#pragma unroll
    for (int o = 16; o; o >>= 1) sum += __shfl_xor_sync(0xffffffffu, sum, o);
    if (lane == 0) g_inv_s[row] = (float)(1.0 / sqrt((double)sum + 1e-8));
}

// fp32 -> fp16 hi parts only; destinations resolved IN DEVICE CODE.
__global__ void split_hi_kernel(const float* __restrict__ X, int which, int n4) {
    int i = blockIdx.x * blockDim.x + threadIdx.x;
    if (i >= n4) return;
    __half* hi = which ? g_S_hi : g_C_hi;
    float4 v = ((const float4*)X)[i];
    __half h0 = __float2half_rn(v.x);
    __half h1 = __float2half_rn(v.y);
    __half h2 = __float2half_rn(v.z);
    __half h3 = __float2half_rn(v.w);
    ushort4 hp;
    hp.x = *(unsigned short*)&h0; hp.y = *(unsigned short*)&h1;
    hp.z = *(unsigned short*)&h2; hp.w = *(unsigned short*)&h3;
    ((ushort4*)hi)[i] = hp;
}

// ---------------- phase 1: hi*hi GEMM + running max + candidate append ----------------
// 512 threads: 16 warps in a 4(M) x 4(N) grid, 32x64 tile per warp.
__global__ __launch_bounds__(NTHREADS, 1) void sim_filter_kernel() {
    extern __shared__ __align__(16) char sbuf[];
    const uint32_t sb = smem_u32(sbuf);

    const int tid = threadIdx.x;
    const int wid = tid >> 5;
    const int lid = tid & 31;
    const int wm  = wid >> 2;          // 0..3 : 32-row M quarter
    const int wn  = wid & 3;           // 0..3 : 64-col N quarter
    const int m_base = blockIdx.x * BM;

    // ldmatrix lane offsets (within-tile byte offsets)
    const uint32_t a_lane = (uint32_t)(lid & 15) * STR + (uint32_t)(lid >> 4) * 16;
    const uint32_t b_lane = (uint32_t)(((lid >> 4) << 3) + (lid & 7)) * STR
                          + (uint32_t)((lid >> 3) & 1) * 16;

    auto issue_loads = [&](int g) {
        const int kk = g % KCH;
        const int t  = g / KCH;
        const uint32_t st = sb + (g % NSTAGE) * STAGE;
#pragma unroll
        for (int i = 0; i < 2; i++) {           // A: 1024 x 16B
            const int o = i * NTHREADS + tid;
            const int row = o >> 3, seg = o & 7;
            cp16(st + row * STR + seg * 16,
                 g_C_hi + (size_t)(m_base + row) * DD + kk * BK + seg * 8);
        }
#pragma unroll
        for (int i = 0; i < 4; i++) {           // B: 2048 x 16B
            const int o = i * NTHREADS + tid;
            const int row = o >> 3, seg = o & 7;
            cp16(st + A_TILE + row * STR + seg * 16,
                 g_S_hi + (size_t)(t * BN + row) * DD + kk * BK + seg * 8);
        }
        CP_COMMIT();
    };

    float bestV[4];
#pragma unroll
    for (int i = 0; i < 4; i++) bestV[i] = -3.0e38f;
    const int r_base = m_base + wm * 32 + (lid >> 2);   // rows: +mf*16 (+8)

    float acc[2][8][4];
#pragma unroll
    for (int mf = 0; mf < 2; mf++)
#pragma unroll
        for (int nf = 0; nf < 8; nf++)
#pragma unroll
            for (int q = 0; q < 4; q++) acc[mf][nf][q] = 0.f;

    auto upd = [&](float v, int col, int row, int k) {
        if (v >= bestV[k] - TAU) {
            int idx = atomicAdd(&g_cnt[row], 1);
            if (idx < CAP)
                g_cand[(size_t)row * CAP + idx] =
                    ((unsigned long long)__float_as_uint(v) << 32) | (unsigned)col;
            if (v > bestV[k]) bestV[k] = v;
        }
    };

    issue_loads(0);
    issue_loads(1);

#pragma unroll 1
    for (int g = 0; g < GTOT; ++g) {
        CP_WAIT1();
        __syncthreads();
        if (g + 2 < GTOT) issue_loads(g + 2);
        else CP_COMMIT();

        const uint32_t aS = sb + (g % NSTAGE) * STAGE;
        const uint32_t bS = aS + A_TILE;

#pragma unroll
        for (int ks = 0; ks < 4; ks++) {
            uint32_t b[4][4];
#pragma unroll
            for (int ng = 0; ng < 4; ng++)
                ldsm_x4(b[ng], bS + (wn * 64 + ng * 16) * STR + ks * 32 + b_lane);
            uint32_t a[2][4];
#pragma unroll
            for (int mf = 0; mf < 2; mf++)
                ldsm_x4(a[mf], aS + (wm * 32 + mf * 16) * STR + ks * 32 + a_lane);
#pragma unroll
            for (int mf = 0; mf < 2; mf++)
#pragma unroll
                for (int nf = 0; nf < 8; nf++)
                    mma16816(acc[mf][nf], a[mf],
                             b[nf >> 1][(nf & 1) * 2], b[nf >> 1][(nf & 1) * 2 + 1]);
        }

        // end of an N-tile: scale, running max + candidate append, reset acc
        if (g % KCH == KCH - 1) {
            const int nt_c = g / KCH;
#pragma unroll
            for (int nf = 0; nf < 8; nf++) {
                const int col0 = nt_c * BN + wn * 64 + nf * 8 + 2 * (lid & 3);
                const float inv0 = __ldg(&g_inv_s[col0]);
                const float inv1 = __ldg(&g_inv_s[col0 + 1]);
#pragma unroll
                for (int mf = 0; mf < 2; mf++) {
                    const int r0 = r_base + mf * 16;
                    upd(acc[mf][nf][0] * inv0, col0,     r0,     2 * mf);
                    upd(acc[mf][nf][1] * inv1, col0 + 1, r0,     2 * mf);
                    upd(acc[mf][nf][2] * inv0, col0,     r0 + 8, 2 * mf + 1);
                    upd(acc[mf][nf][3] * inv1, col0 + 1, r0 + 8, 2 * mf + 1);
                }
            }
#pragma unroll
            for (int mf = 0; mf < 2; mf++)
#pragma unroll
                for (int nf = 0; nf < 8; nf++)
#pragma unroll
                    for (int q = 0; q < 4; q++) acc[mf][nf][q] = 0.f;
        }
    }

    // ---- merge per-row approx max through smem -> g_rowmax ----
    __syncthreads();
    float* M = (float*)sbuf;                       // 128 rows x 16 slots
    const int slot = wn * 4 + (lid & 3);
#pragma unroll
    for (int i = 0; i < 4; i++) {
        const int rl = wm * 32 + (i >> 1) * 16 + (lid >> 2) + (i & 1) * 8;
        M[rl * 16 + slot] = bestV[i];
    }
    __syncthreads();
    if (tid < 128) {
        float best = M[tid * 16];
#pragma unroll
        for (int s = 1; s < 16; s++) best = fmaxf(best, M[tid * 16 + s]);
        g_rowmax[m_base + tid] = best;
    }
}

// ---------------- phase 2: exact fp32 refine of survivors + gather ----------------
__global__ __launch_bounds__(128) void refine_kernel(const float* __restrict__ C,
                                                     const float* __restrict__ S,
                                                     float* __restrict__ out) {
    const int row = blockIdx.x;
    const int tid = threadIdx.x;

    __shared__ float cs[DD];
    __shared__ int   s_surv[64];
    __shared__ int   s_nsurv;
    __shared__ float s_red[4];
    __shared__ unsigned long long s_best;

    for (int i = tid; i < DD; i += 128) cs[i] = C[(size_t)row * DD + i];
    if (tid == 0) { s_nsurv = 0; s_best = 0ULL; }
    __syncthreads();

    const int cnt = g_cnt[row];
    bool fallback = (cnt > CAP);

    if (!fallback) {
        const float thr = g_rowmax[row] - TAU;
        for (int i = tid; i < cnt; i += 128) {
            unsigned long long e = g_cand[(size_t)row * CAP + i];
            float v = __uint_as_float((unsigned)(e >> 32));
            if (v >= thr) {
                int k = atomicAdd(&s_nsurv, 1);
                if (k < 64) s_surv[k] = (int)(e & 0xffffffffu);
            }
        }
        __syncthreads();
        if (s_nsurv > 64) fallback = true;
    }
    __syncthreads();

    if (!fallback) {
        const int ns = s_nsurv;
        for (int s = 0; s < ns; s++) {
            const int col = s_surv[s];
            const float* sr = S + (size_t)col * DD;
            float part = 0.f;
            for (int i = tid; i < DD; i += 128) part += cs[i] * sr[i];
#pragma unroll
            for (int o = 16; o; o >>= 1) part += __shfl_xor_sync(0xffffffffu, part, o);
            if ((tid & 31) == 0) s_red[tid >> 5] = part;
            __syncthreads();
            if (tid == 0) {
                float v = (s_red[0] + s_red[1] + s_red[2] + s_red[3]) * g_inv_s[col];
                unsigned u = __float_as_uint(v);
                u = (u & 0x80000000u) ? ~u : (u | 0x80000000u);
                unsigned long long key =
                    ((unsigned long long)u << 32) | (unsigned)(N_S - 1 - col);
                if (key > s_best) s_best = key;
            }
            __syncthreads();
        }
    } else {
        // deterministic full-scan fallback (statistically ~never taken)
        unsigned long long lb = 0ULL;
        for (int col = tid; col < N_S; col += 128) {
            const float* sr = S + (size_t)col * DD;
            float dot = 0.f;
            for (int i = 0; i < DD; i++) dot += cs[i] * sr[i];
            float v = dot * g_inv_s[col];
            unsigned u = __float_as_uint(v);
            u = (u & 0x80000000u) ? ~u : (u | 0x80000000u);
            unsigned long long key =
                ((unsigned long long)u << 32) | (unsigned)(N_S - 1 - col);
            if (key > lb) lb = key;
        }
        atomicMax(&s_best, lb);
        __syncthreads();
    }

    const int bcol = N_S - 1 - (int)(s_best & 0xffffffffu);
    const float4* src = (const float4*)(S + (size_t)bcol * DD);
    float4* dst = (float4*)(out + (size_t)row * DD);
    for (int i = tid; i < DD / 4; i += 128) dst[i] = src[i];
}

extern "C" void kernel_launch(void* const* d_in, const int* in_sizes, int n_in,
                              void* d_out, int out_size) {
    const float* feats_c = (const float*)d_in[0];
    const float* feats_s = (const float*)d_in[1];
    float* out = (float*)d_out;

    cudaFuncSetAttribute(sim_filter_kernel,
                         cudaFuncAttributeMaxDynamicSharedMemorySize, SMEM_TOTAL);

    init_cnt_kernel<<<N_C / 256, 256>>>();
    style_norms_kernel<<<N_S / 8, 256>>>(feats_s);

    const int n4 = N_C * DD / 4;
    split_hi_kernel<<<(n4 + 255) / 256, 256>>>(feats_c, 0, n4);
    split_hi_kernel<<<(n4 + 255) / 256, 256>>>(feats_s, 1, n4);

    sim_filter_kernel<<<N_C / BM, NTHREADS, SMEM_TOTAL>>>();
    refine_kernel<<<N_C, 128>>>(feats_c, feats_s, out);
}

// round 12
// speedup vs baseline: 6.7419x; 1.0214x over previous
#include <cuda_runtime.h>
#include <cuda_fp16.h>
#include <cstdint>

#define N_C 16384
#define N_S 16384
#define DD  2688

#define BM 128
#define BN 256
#define BK 64                     // fp16 per K-chunk (128 B rows)
#define KCH (DD / BK)             // 42
#define NT (N_S / BN)             // 64
#define GTOT (NT * KCH)           // 2688 chunks per CTA

#define STR 144                   // smem row stride: 128B data + 16B pad
#define A_TILE (128 * STR)        // 18432
#define B_TILE (256 * STR)        // 36864
#define STAGE (A_TILE + B_TILE)   // 55296
#define NSTAGE 3
#define SMEM_TOTAL (NSTAGE * STAGE)  // 165888

#define NTHREADS 256              // 8 warps: 2(M) x 4(N), 64x64 tile per warp
#define CAP 384
#define TAU 0.008f

// ---------------- device scratch (symbols only touched in device code) ----------------
__device__ __half g_C_hi[(size_t)N_C * DD];
__device__ __half g_S_hi[(size_t)N_S * DD];
__device__ float g_inv_s[N_S];
__device__ float g_rowmax[N_C];
__device__ int   g_cnt[N_C];
__device__ unsigned long long g_cand[(size_t)N_C * CAP];

// ---------------- helpers ----------------
__device__ __forceinline__ uint32_t smem_u32(const void* p) {
    uint32_t a;
    asm("{ .reg .u64 t; cvta.to.shared.u64 t, %1; cvt.u32.u64 %0, t; }" : "=r"(a) : "l"(p));
    return a;
}
__device__ __forceinline__ void cp16(uint32_t s, const void* g) {
    asm volatile("cp.async.cg.shared.global [%0], [%1], 16;" :: "r"(s), "l"(g));
}
#define CP_COMMIT() asm volatile("cp.async.commit_group;" ::: "memory")
#define CP_WAIT1()  asm volatile("cp.async.wait_group 1;" ::: "memory")

__device__ __forceinline__ void ldsm_x4(uint32_t* r, uint32_t addr) {
    asm volatile("ldmatrix.sync.aligned.m8n8.x4.shared.b16 {%0,%1,%2,%3}, [%4];"
                 : "=r"(r[0]), "=r"(r[1]), "=r"(r[2]), "=r"(r[3]) : "r"(addr));
}
__device__ __forceinline__ void mma16816(float* c, const uint32_t* a,
                                         uint32_t b0, uint32_t b1) {
    asm volatile("mma.sync.aligned.m16n8k16.row.col.f32.f16.f16.f32 "
                 "{%0,%1,%2,%3}, {%4,%5,%6,%7}, {%8,%9}, {%0,%1,%2,%3};"
                 : "+f"(c[0]), "+f"(c[1]), "+f"(c[2]), "+f"(c[3])
                 : "r"(a[0]), "r"(a[1]), "r"(a[2]), "r"(a[3]), "r"(b0), "r"(b1));
}

// ---------------- small kernels ----------------
__global__ void init_cnt_kernel() {
    int i = blockIdx.x * blockDim.x + threadIdx.x;
    if (i < N_C) g_cnt[i] = 0;
}

__global__ void style_norms_kernel(const float* __restrict__ S) {
    int row  = blockIdx.x * 8 + (threadIdx.x >> 5);
    int lane = threadIdx.x & 31;
    const float4* p = (const float4*)(S + (size_t)row * DD);
    float sum = 0.f;
    for (int i = lane; i < DD / 4; i += 32) {
        float4 v = p[i];
        sum += v.x * v.x + v.y * v.y + v.z * v.z + v.w * v.w;
    }
#pragma unroll
    for (int o = 16; o; o >>= 1) sum += __shfl_xor_sync(0xffffffffu, sum, o);
    if (lane == 0) g_inv_s[row] = (float)(1.0 / sqrt((double)sum + 1e-8));
}

// fp32 -> fp16 hi parts; destinations resolved IN DEVICE CODE.
__global__ void split_hi_kernel(const float* __restrict__ X, int which, int n4) {
    int i = blockIdx.x * blockDim.x + threadIdx.x;
    if (i >= n4) return;
    __half* hi = which ? g_S_hi : g_C_hi;
    float4 v = ((const float4*)X)[i];
    __half h0 = __float2half_rn(v.x);
    __half h1 = __float2half_rn(v.y);
    __half h2 = __float2half_rn(v.z);
    __half h3 = __float2half_rn(v.w);
    ushort4 hp;
    hp.x = *(unsigned short*)&h0; hp.y = *(unsigned short*)&h1;
    hp.z = *(unsigned short*)&h2; hp.w = *(unsigned short*)&h3;
    ((ushort4*)hi)[i] = hp;
}

// ---------------- phase 1: fp16 GEMM + running max + candidate append ----------------
// 256 threads: 8 warps in a 2(M) x 4(N) grid, 64x64 tile per warp.
__global__ __launch_bounds__(NTHREADS, 1) void sim_filter_kernel() {
    extern __shared__ __align__(16) char sbuf[];
    const uint32_t sb = smem_u32(sbuf);

    const int tid = threadIdx.x;
    const int wid = tid >> 5;
    const int lid = tid & 31;
    const int wm  = wid >> 2;          // 0..1 : 64-row M half
    const int wn  = wid & 3;           // 0..3 : 64-col N quarter
    const int m_base = blockIdx.x * BM;

    // ldmatrix lane offsets (within-tile byte offsets)
    const uint32_t a_lane = (uint32_t)(lid & 15) * STR + (uint32_t)(lid >> 4) * 16;
    const uint32_t b_lane = (uint32_t)(((lid >> 4) << 3) + (lid & 7)) * STR
                          + (uint32_t)((lid >> 3) & 1) * 16;

    auto issue_loads = [&](int g) {
        const int kk = g % KCH;
        const int t  = g / KCH;
        const uint32_t st = sb + (g % NSTAGE) * STAGE;
#pragma unroll
        for (int i = 0; i < 4; i++) {           // A: 1024 x 16B
            const int o = i * NTHREADS + tid;
            const int row = o >> 3, seg = o & 7;
            cp16(st + row * STR + seg * 16,
                 g_C_hi + (size_t)(m_base + row) * DD + kk * BK + seg * 8);
        }
#pragma unroll
        for (int i = 0; i < 8; i++) {           // B: 2048 x 16B
            const int o = i * NTHREADS + tid;
            const int row = o >> 3, seg = o & 7;
            cp16(st + A_TILE + row * STR + seg * 16,
                 g_S_hi + (size_t)(t * BN + row) * DD + kk * BK + seg * 8);
        }
        CP_COMMIT();
    };

    float bestV[8];
#pragma unroll
    for (int i = 0; i < 8; i++) bestV[i] = -3.0e38f;
    const int r_base = m_base + wm * 64 + (lid >> 2);   // rows: +mf*16 (+8)

    float acc[4][8][4];
#pragma unroll
    for (int mf = 0; mf < 4; mf++)
#pragma unroll
        for (int nf = 0; nf < 8; nf++)
#pragma unroll
            for (int q = 0; q < 4; q++) acc[mf][nf][q] = 0.f;

    auto upd = [&](float v, int col, int row, int k) {
        if (v >= bestV[k] - TAU) {
            int idx = atomicAdd(&g_cnt[row], 1);
            if (idx < CAP)
                g_cand[(size_t)row * CAP + idx] =
                    ((unsigned long long)__float_as_uint(v) << 32) | (unsigned)col;
            if (v > bestV[k]) bestV[k] = v;
        }
    };

    issue_loads(0);
    issue_loads(1);

#pragma unroll 1
    for (int g = 0; g < GTOT; ++g) {
        CP_WAIT1();                    // my group g complete
        __syncthreads();               // ALL threads' group g complete + visible
        if (g + 2 < GTOT) issue_loads(g + 2);   // stage (g+2)%3: consumed at g-1
        else CP_COMMIT();

        const uint32_t aS = sb + (g % NSTAGE) * STAGE;
        const uint32_t bS = aS + A_TILE;

#pragma unroll
        for (int ks = 0; ks < 4; ks++) {
            uint32_t b[4][4];
#pragma unroll
            for (int ng = 0; ng < 4; ng++)
                ldsm_x4(b[ng], bS + (wn * 64 + ng * 16) * STR + ks * 32 + b_lane);
            uint32_t a[4][4];
#pragma unroll
            for (int mf = 0; mf < 4; mf++)
                ldsm_x4(a[mf], aS + (wm * 64 + mf * 16) * STR + ks * 32 + a_lane);
#pragma unroll
            for (int mf = 0; mf < 4; mf++)
#pragma unroll
                for (int nf = 0; nf < 8; nf++)
                    mma16816(acc[mf][nf], a[mf],
                             b[nf >> 1][(nf & 1) * 2], b[nf >> 1][(nf & 1) * 2 + 1]);
        }

        // end of an N-tile: scale, running max + candidate append, reset acc
        if (g % KCH == KCH - 1) {
            const int nt_c = g / KCH;
#pragma unroll
            for (int nf = 0; nf < 8; nf++) {
                const int col0 = nt_c * BN + wn * 64 + nf * 8 + 2 * (lid & 3);
                const float inv0 = __ldg(&g_inv_s[col0]);
                const float inv1 = __ldg(&g_inv_s[col0 + 1]);
#pragma unroll
                for (int mf = 0; mf < 4; mf++) {
                    const int r0 = r_base + mf * 16;
                    upd(acc[mf][nf][0] * inv0, col0,     r0,     2 * mf);
                    upd(acc[mf][nf][1] * inv1, col0 + 1, r0,     2 * mf);
                    upd(acc[mf][nf][2] * inv0, col0,     r0 + 8, 2 * mf + 1);
                    upd(acc[mf][nf][3] * inv1, col0 + 1, r0 + 8, 2 * mf + 1);
                }
            }
#pragma unroll
            for (int mf = 0; mf < 4; mf++)
#pragma unroll
                for (int nf = 0; nf < 8; nf++)
#pragma unroll
                    for (int q = 0; q < 4; q++) acc[mf][nf][q] = 0.f;
        }
    }

    // ---- merge per-row approx max through smem -> g_rowmax ----
    __syncthreads();
    float* M = (float*)sbuf;                       // 128 rows x 16 slots
    const int slot = wn * 4 + (lid & 3);
#pragma unroll
    for (int i = 0; i < 8; i++) {
        const int rl = wm * 64 + (i >> 1) * 16 + (lid >> 2) + (i & 1) * 8;
        M[rl * 16 + slot] = bestV[i];
    }
    __syncthreads();
    if (tid < 128) {
        float best = M[tid * 16];
#pragma unroll
        for (int s = 1; s < 16; s++) best = fmaxf(best, M[tid * 16 + s]);
        g_rowmax[m_base + tid] = best;
    }
}

// ---------------- phase 2: exact fp32 refine of survivors + gather ----------------
__global__ __launch_bounds__(128) void refine_kernel(const float* __restrict__ C,
                                                     const float* __restrict__ S,
                                                     float* __restrict__ out) {
    const int row = blockIdx.x;
    const int tid = threadIdx.x;

    __shared__ float cs[DD];
    __shared__ int   s_surv[64];
    __shared__ int   s_nsurv;
    __shared__ float s_red[4];
    __shared__ unsigned long long s_best;

    for (int i = tid; i < DD; i += 128) cs[i] = C[(size_t)row * DD + i];
    if (tid == 0) { s_nsurv = 0; s_best = 0ULL; }
    __syncthreads();

    const int cnt = g_cnt[row];
    bool fallback = (cnt > CAP);

    if (!fallback) {
        const float thr = g_rowmax[row] - TAU;
        for (int i = tid; i < cnt; i += 128) {
            unsigned long long e = g_cand[(size_t)row * CAP + i];
            float v = __uint_as_float((unsigned)(e >> 32));
            if (v >= thr) {
                int k = atomicAdd(&s_nsurv, 1);
                if (k < 64) s_surv[k] = (int)(e & 0xffffffffu);
            }
        }
        __syncthreads();
        if (s_nsurv > 64) fallback = true;
    }
    __syncthreads();

    if (!fallback) {
        const int ns = s_nsurv;
        for (int s = 0; s < ns; s++) {
            const int col = s_surv[s];
            const float* sr = S + (size_t)col * DD;
            float part = 0.f;
            for (int i = tid; i < DD; i += 128) part += cs[i] * sr[i];
#pragma unroll
            for (int o = 16; o; o >>= 1) part += __shfl_xor_sync(0xffffffffu, part, o);
            if ((tid & 31) == 0) s_red[tid >> 5] = part;
            __syncthreads();
            if (tid == 0) {
                float v = (s_red[0] + s_red[1] + s_red[2] + s_red[3]) * g_inv_s[col];
                unsigned u = __float_as_uint(v);
                u = (u & 0x80000000u) ? ~u : (u | 0x80000000u);
                unsigned long long key =
                    ((unsigned long long)u << 32) | (unsigned)(N_S - 1 - col);
                if (key > s_best) s_best = key;
            }
            __syncthreads();
        }
    } else {
        // deterministic full-scan fallback (statistically ~never taken)
        unsigned long long lb = 0ULL;
        for (int col = tid; col < N_S; col += 128) {
            const float* sr = S + (size_t)col * DD;
            float dot = 0.f;
            for (int i = 0; i < DD; i++) dot += cs[i] * sr[i];
            float v = dot * g_inv_s[col];
            unsigned u = __float_as_uint(v);
            u = (u & 0x80000000u) ? ~u : (u | 0x80000000u);
            unsigned long long key =
                ((unsigned long long)u << 32) | (unsigned)(N_S - 1 - col);
            if (key > lb) lb = key;
        }
        atomicMax(&s_best, lb);
        __syncthreads();
    }

    const int bcol = N_S - 1 - (int)(s_best & 0xffffffffu);
    const float4* src = (const float4*)(S + (size_t)bcol * DD);
    float4* dst = (float4*)(out + (size_t)row * DD);
    for (int i = tid; i < DD / 4; i += 128) dst[i] = src[i];
}

extern "C" void kernel_launch(void* const* d_in, const int* in_sizes, int n_in,
                              void* d_out, int out_size) {
    const float* feats_c = (const float*)d_in[0];
    const float* feats_s = (const float*)d_in[1];
    float* out = (float*)d_out;

    cudaFuncSetAttribute(sim_filter_kernel,
                         cudaFuncAttributeMaxDynamicSharedMemorySize, SMEM_TOTAL);

    init_cnt_kernel<<<N_C / 256, 256>>>();
    style_norms_kernel<<<N_S / 8, 256>>>(feats_s);

    const int n4 = N_C * DD / 4;
    split_hi_kernel<<<(n4 + 255) / 256, 256>>>(feats_c, 0, n4);
    split_hi_kernel<<<(n4 + 255) / 256, 256>>>(feats_s, 1, n4);

    sim_filter_kernel<<<N_C / BM, NTHREADS, SMEM_TOTAL>>>();
    refine_kernel<<<N_C, 128>>>(feats_c, feats_s, out);
}

// round 13
// speedup vs baseline: 6.7875x; 1.0068x over previous
#include <cuda_runtime.h>
#include <cuda_fp16.h>
#include <cstdint>

#define N_C 16384
#define N_S 16384
#define DD  2688

#define BM 128
#define BN 128
#define BK 64                     // fp16 per K-chunk (128 B rows)
#define KCH (DD / BK)             // 42
#define NTB ((N_S / 2) / BN)      // 64 N-tiles per CTA (one half)
#define GTOT (NTB * KCH)          // 2688 chunks per CTA

#define STR 144                   // smem row stride: 128B data + 16B pad
#define A_TILE (128 * STR)        // 18432
#define B_TILE (128 * STR)        // 18432
#define STAGE (A_TILE + B_TILE)   // 36864
#define NSTAGE 3
#define SMEM_TOTAL (NSTAGE * STAGE)  // 110592 -> 2 CTAs/SM

#define NTHREADS 256              // 8 warps: 2(M) x 4(N), 64x32 tile per warp
#define CAP 384
#define TAU 0.008f

// ---------------- device scratch (symbols only touched in device code) ----------------
__device__ __half g_C_hi[(size_t)N_C * DD];
__device__ __half g_S_hi[(size_t)N_S * DD];
__device__ float g_inv_s[N_S];
__device__ unsigned g_rowmax_u[N_C];      // monotonic-encoded float, atomicMax-merged
__device__ int   g_cnt[N_C];
__device__ unsigned long long g_cand[(size_t)N_C * CAP];

// ---------------- helpers ----------------
__device__ __forceinline__ uint32_t smem_u32(const void* p) {
    uint32_t a;
    asm("{ .reg .u64 t; cvta.to.shared.u64 t, %1; cvt.u32.u64 %0, t; }" : "=r"(a) : "l"(p));
    return a;
}
__device__ __forceinline__ void cp16(uint32_t s, const void* g) {
    asm volatile("cp.async.cg.shared.global [%0], [%1], 16;" :: "r"(s), "l"(g));
}
#define CP_COMMIT() asm volatile("cp.async.commit_group;" ::: "memory")
#define CP_WAIT1()  asm volatile("cp.async.wait_group 1;" ::: "memory")

__device__ __forceinline__ void ldsm_x4(uint32_t* r, uint32_t addr) {
    asm volatile("ldmatrix.sync.aligned.m8n8.x4.shared.b16 {%0,%1,%2,%3}, [%4];"
                 : "=r"(r[0]), "=r"(r[1]), "=r"(r[2]), "=r"(r[3]) : "r"(addr));
}
__device__ __forceinline__ void mma16816(float* c, const uint32_t* a,
                                         uint32_t b0, uint32_t b1) {
    asm volatile("mma.sync.aligned.m16n8k16.row.col.f32.f16.f16.f32 "
                 "{%0,%1,%2,%3}, {%4,%5,%6,%7}, {%8,%9}, {%0,%1,%2,%3};"
                 : "+f"(c[0]), "+f"(c[1]), "+f"(c[2]), "+f"(c[3])
                 : "r"(a[0]), "r"(a[1]), "r"(a[2]), "r"(a[3]), "r"(b0), "r"(b1));
}
__device__ __forceinline__ unsigned mono_enc(float v) {
    unsigned u = __float_as_uint(v);
    return (u & 0x80000000u) ? ~u : (u | 0x80000000u);
}
__device__ __forceinline__ float mono_dec(unsigned u) {
    unsigned b = (u & 0x80000000u) ? (u ^ 0x80000000u) : ~u;
    return __uint_as_float(b);
}

// ---------------- small kernels ----------------
__global__ void init_kernel() {
    int i = blockIdx.x * blockDim.x + threadIdx.x;
    if (i < N_C) { g_cnt[i] = 0; g_rowmax_u[i] = 0u; }  // 0 = very negative float
}

__global__ void style_norms_kernel(const float* __restrict__ S) {
    int row  = blockIdx.x * 8 + (threadIdx.x >> 5);
    int lane = threadIdx.x & 31;
    const float4* p = (const float4*)(S + (size_t)row * DD);
    float sum = 0.f;
    for (int i = lane; i < DD / 4; i += 32) {
        float4 v = p[i];
        sum += v.x * v.x + v.y * v.y + v.z * v.z + v.w * v.w;
    }
#pragma unroll
    for (int o = 16; o; o >>= 1) sum += __shfl_xor_sync(0xffffffffu, sum, o);
    if (lane == 0) g_inv_s[row] = (float)(1.0 / sqrt((double)sum + 1e-8));
}

// fp32 -> fp16 hi parts; destinations resolved IN DEVICE CODE.
__global__ void split_hi_kernel(const float* __restrict__ X, int which, int n4) {
    int i = blockIdx.x * blockDim.x + threadIdx.x;
    if (i >= n4) return;
    __half* hi = which ? g_S_hi : g_C_hi;
    float4 v = ((const float4*)X)[i];
    __half h0 = __float2half_rn(v.x);
    __half h1 = __float2half_rn(v.y);
    __half h2 = __float2half_rn(v.z);
    __half h3 = __float2half_rn(v.w);
    ushort4 hp;
    hp.x = *(unsigned short*)&h0; hp.y = *(unsigned short*)&h1;
    hp.z = *(unsigned short*)&h2; hp.w = *(unsigned short*)&h3;
    ((ushort4*)hi)[i] = hp;
}

// ---------------- phase 1: fp16 GEMM + running max + candidate append ----------------
// grid (128 M-tiles, 2 N-halves); 256 threads: 8 warps, 2(M) x 4(N), 64x32 per warp.
__global__ __launch_bounds__(NTHREADS, 2) void sim_filter_kernel() {
    extern __shared__ __align__(16) char sbuf[];
    const uint32_t sb = smem_u32(sbuf);

    const int tid = threadIdx.x;
    const int wid = tid >> 5;
    const int lid = tid & 31;
    const int wm  = wid >> 2;          // 0..1 : 64-row M half
    const int wn  = wid & 3;           // 0..3 : 32-col N quarter
    const int m_base = blockIdx.x * BM;
    const int s_base = blockIdx.y * (N_S / 2);

    // ldmatrix lane offsets (within-tile byte offsets)
    const uint32_t a_lane = (uint32_t)(lid & 15) * STR + (uint32_t)(lid >> 4) * 16;
    const uint32_t b_lane = (uint32_t)(((lid >> 4) << 3) + (lid & 7)) * STR
                          + (uint32_t)((lid >> 3) & 1) * 16;

    auto issue_loads = [&](int g) {
        const int kk = g % KCH;
        const int t  = g / KCH;
        const uint32_t st = sb + (g % NSTAGE) * STAGE;
#pragma unroll
        for (int i = 0; i < 4; i++) {           // A: 1024 x 16B
            const int o = i * NTHREADS + tid;
            const int row = o >> 3, seg = o & 7;
            cp16(st + row * STR + seg * 16,
                 g_C_hi + (size_t)(m_base + row) * DD + kk * BK + seg * 8);
        }
#pragma unroll
        for (int i = 0; i < 4; i++) {           // B: 1024 x 16B
            const int o = i * NTHREADS + tid;
            const int row = o >> 3, seg = o & 7;
            cp16(st + A_TILE + row * STR + seg * 16,
                 g_S_hi + (size_t)(s_base + t * BN + row) * DD + kk * BK + seg * 8);
        }
        CP_COMMIT();
    };

    float bestV[8];
#pragma unroll
    for (int i = 0; i < 8; i++) bestV[i] = -3.0e38f;
    const int r_base = m_base + wm * 64 + (lid >> 2);   // rows: +mf*16 (+8)

    float acc[4][4][4];
#pragma unroll
    for (int mf = 0; mf < 4; mf++)
#pragma unroll
        for (int nf = 0; nf < 4; nf++)
#pragma unroll
            for (int q = 0; q < 4; q++) acc[mf][nf][q] = 0.f;

    auto upd = [&](float v, int col, int row, int k) {
        if (v >= bestV[k] - TAU) {
            int idx = atomicAdd(&g_cnt[row], 1);
            if (idx < CAP)
                g_cand[(size_t)row * CAP + idx] =
                    ((unsigned long long)__float_as_uint(v) << 32) | (unsigned)col;
            if (v > bestV[k]) bestV[k] = v;
        }
    };

    issue_loads(0);
    issue_loads(1);

#pragma unroll 1
    for (int g = 0; g < GTOT; ++g) {
        CP_WAIT1();                    // my group g complete
        __syncthreads();               // ALL threads' group g complete + visible
        if (g + 2 < GTOT) issue_loads(g + 2);   // stage (g+2)%3: consumed at g-1
        else CP_COMMIT();

        const uint32_t aS = sb + (g % NSTAGE) * STAGE;
        const uint32_t bS = aS + A_TILE;

#pragma unroll
        for (int ks = 0; ks < 4; ks++) {
            uint32_t b[2][4];
#pragma unroll
            for (int ng = 0; ng < 2; ng++)
                ldsm_x4(b[ng], bS + (wn * 32 + ng * 16) * STR + ks * 32 + b_lane);
            uint32_t a[4][4];
#pragma unroll
            for (int mf = 0; mf < 4; mf++)
                ldsm_x4(a[mf], aS + (wm * 64 + mf * 16) * STR + ks * 32 + a_lane);
#pragma unroll
            for (int mf = 0; mf < 4; mf++)
#pragma unroll
                for (int nf = 0; nf < 4; nf++)
                    mma16816(acc[mf][nf], a[mf],
                             b[nf >> 1][(nf & 1) * 2], b[nf >> 1][(nf & 1) * 2 + 1]);
        }

        // end of an N-tile: scale, running max + candidate append, reset acc
        if (g % KCH == KCH - 1) {
            const int nt_c = g / KCH;
#pragma unroll
            for (int nf = 0; nf < 4; nf++) {
                const int col0 = s_base + nt_c * BN + wn * 32 + nf * 8 + 2 * (lid & 3);
                const float inv0 = __ldg(&g_inv_s[col0]);
                const float inv1 = __ldg(&g_inv_s[col0 + 1]);
#pragma unroll
                for (int mf = 0; mf < 4; mf++) {
                    const int r0 = r_base + mf * 16;
                    upd(acc[mf][nf][0] * inv0, col0,     r0,     2 * mf);
                    upd(acc[mf][nf][1] * inv1, col0 + 1, r0,     2 * mf);
                    upd(acc[mf][nf][2] * inv0, col0,     r0 + 8, 2 * mf + 1);
                    upd(acc[mf][nf][3] * inv1, col0 + 1, r0 + 8, 2 * mf + 1);
                }
            }
#pragma unroll
            for (int mf = 0; mf < 4; mf++)
#pragma unroll
                for (int nf = 0; nf < 4; nf++)
#pragma unroll
                    for (int q = 0; q < 4; q++) acc[mf][nf][q] = 0.f;
        }
    }

    // ---- merge per-row approx max through smem, atomicMax into g_rowmax_u ----
    __syncthreads();
    float* M = (float*)sbuf;                       // 128 rows x 16 slots
    const int slot = wn * 4 + (lid & 3);
#pragma unroll
    for (int i = 0; i < 8; i++) {
        const int rl = wm * 64 + (i >> 1) * 16 + (lid >> 2) + (i & 1) * 8;
        M[rl * 16 + slot] = bestV[i];
    }
    __syncthreads();
    if (tid < 128) {
        float best = M[tid * 16];
#pragma unroll
        for (int s = 1; s < 16; s++) best = fmaxf(best, M[tid * 16 + s]);
        atomicMax(&g_rowmax_u[m_base + tid], mono_enc(best));
    }
}

// ---------------- phase 2: exact fp32 refine of survivors + gather ----------------
__global__ __launch_bounds__(128) void refine_kernel(const float* __restrict__ C,
                                                     const float* __restrict__ S,
                                                     float* __restrict__ out) {
    const int row = blockIdx.x;
    const int tid = threadIdx.x;

    __shared__ float cs[DD];
    __shared__ int   s_surv[64];
    __shared__ int   s_nsurv;
    __shared__ float s_red[4];
    __shared__ unsigned long long s_best;

    for (int i = tid; i < DD; i += 128) cs[i] = C[(size_t)row * DD + i];
    if (tid == 0) { s_nsurv = 0; s_best = 0ULL; }
    __syncthreads();

    const int cnt = g_cnt[row];
    bool fallback = (cnt > CAP);

    if (!fallback) {
        const float thr = mono_dec(g_rowmax_u[row]) - TAU;
        for (int i = tid; i < cnt; i += 128) {
            unsigned long long e = g_cand[(size_t)row * CAP + i];
            float v = __uint_as_float((unsigned)(e >> 32));
            if (v >= thr) {
                int k = atomicAdd(&s_nsurv, 1);
                if (k < 64) s_surv[k] = (int)(e & 0xffffffffu);
            }
        }
        __syncthreads();
        if (s_nsurv > 64) fallback = true;
    }
    __syncthreads();

    if (!fallback) {
        const int ns = s_nsurv;
        for (int s = 0; s < ns; s++) {
            const int col = s_surv[s];
            const float* sr = S + (size_t)col * DD;
            float part = 0.f;
            for (int i = tid; i < DD; i += 128) part += cs[i] * sr[i];
#pragma unroll
            for (int o = 16; o; o >>= 1) part += __shfl_xor_sync(0xffffffffu, part, o);
            if ((tid & 31) == 0) s_red[tid >> 5] = part;
            __syncthreads();
            if (tid == 0) {
                float v = (s_red[0] + s_red[1] + s_red[2] + s_red[3]) * g_inv_s[col];
                unsigned long long key =
                    ((unsigned long long)mono_enc(v) << 32) | (unsigned)(N_S - 1 - col);
                if (key > s_best) s_best = key;
            }
            __syncthreads();
        }
    } else {
        // deterministic full-scan fallback (statistically ~never taken)
        unsigned long long lb = 0ULL;
        for (int col = tid; col < N_S; col += 128) {
            const float* sr = S + (size_t)col * DD;
            float dot = 0.f;
            for (int i = 0; i < DD; i++) dot += cs[i] * sr[i];
            float v = dot * g_inv_s[col];
            unsigned long long key =
                ((unsigned long long)mono_enc(v) << 32) | (unsigned)(N_S - 1 - col);
            if (key > lb) lb = key;
        }
        atomicMax(&s_best, lb);
        __syncthreads();
    }

    const int bcol = N_S - 1 - (int)(s_best & 0xffffffffu);
    const float4* src = (const float4*)(S + (size_t)bcol * DD);
    float4* dst = (float4*)(out + (size_t)row * DD);
    for (int i = tid; i < DD / 4; i += 128) dst[i] = src[i];
}

extern "C" void kernel_launch(void* const* d_in, const int* in_sizes, int n_in,
                              void* d_out, int out_size) {
    const float* feats_c = (const float*)d_in[0];
    const float* feats_s = (const float*)d_in[1];
    float* out = (float*)d_out;

    cudaFuncSetAttribute(sim_filter_kernel,
                         cudaFuncAttributeMaxDynamicSharedMemorySize, SMEM_TOTAL);

    init_kernel<<<N_C / 256, 256>>>();
    style_norms_kernel<<<N_S / 8, 256>>>(feats_s);

    const int n4 = N_C * DD / 4;
    split_hi_kernel<<<(n4 + 255) / 256, 256>>>(feats_c, 0, n4);
    split_hi_kernel<<<(n4 + 255) / 256, 256>>>(feats_s, 1, n4);

    dim3 grid(N_C / BM, 2);
    sim_filter_kernel<<<grid, NTHREADS, SMEM_TOTAL>>>();
    refine_kernel<<<N_C, 128>>>(feats_c, feats_s, out);
}